// round 15
// baseline (speedup 1.0000x reference)
#include <cuda_runtime.h>
#include <cstdint>

// AttentionDownsampler v13: v9's proven kernels, chunked & stream-pipelined.
// 4 chunks of 32 slabs. Stream A runs K1 chunks, stream B runs K3 chunks;
// K3(i) waits on event from K1(i). K3(i) overlaps K1(i+1), and K3(i)'s hr
// reads hit L2 (chunk = 38MB, freshly pulled by K1(i)). Fork/join is done
// with events inside graph capture -- scheduler-enforced, no spins.

#define DIM     384
#define KS      7
#define NP      49
#define HW      112
#define PLANE   (HW * HW)
#define PLANE4  (PLANE / 4)
#define FN      16
#define NSLAB   128
#define SLABPIX 784
#define DROP_P  0.2f

#define NCHUNK  4
#define SLABS_C (NSLAB / NCHUNK)  // 32 slabs per chunk

#define CPGO    32
#define NCG2    12
#define T3      448               // (x4:28, cc:16)

__device__ float g_attnT[(size_t)NSLAB * SLABPIX];  // [slab][dy*112 + x]

// ================= K1: pixel dot + softmax (half-slab CTAs) ==============
__global__ void __launch_bounds__(392, 2)
k1_dot_softmax(const float* __restrict__ hr,
               const float* __restrict__ du,
               const float* __restrict__ aw,
               const float* __restrict__ ab,
               const float* __restrict__ wmat,
               const float* __restrict__ bmat,
               int slab_base)
{
    __shared__ float awsh[DIM];
    __shared__ float pd_s[392];

    const int bid  = blockIdx.x;
    const int xh   = bid & 1;
    const int slab = slab_base + (bid >> 1);
    const int ph   = slab & (FN - 1);
    const int b    = slab >> 4;

    const int tid = threadIdx.x;         // tid = qr*98 + dy*14 + x4l
    const int qr  = tid / 98;
    const int pos = tid - qr * 98;
    const int dy  = pos / 14;
    const int x4l = pos - dy * 14;

    if (tid < DIM) awsh[tid] = __ldg(aw + tid);
    pd_s[tid] = 0.f;
    __syncthreads();

    const float4* gp = (const float4*)(hr
        + (size_t)(b * DIM + qr * 96) * PLANE
        + (size_t)(ph * KS + dy) * HW) + (xh * 14 + x4l);
    const float* ap = awsh + qr * 96;
    float4 acc = make_float4(0.f, 0.f, 0.f, 0.f);
    #pragma unroll 8
    for (int t = 0; t < 96; t++) {
        float4 v = __ldg(gp + (size_t)t * PLANE4);
        const float a = ap[t];
        acc.x = fmaf(v.x, a, acc.x);
        acc.y = fmaf(v.y, a, acc.y);
        acc.z = fmaf(v.z, a, acc.z);
        acc.w = fmaf(v.w, a, acc.w);
    }
    {
        float* pc = pd_s + dy * 56 + x4l * 4;
        atomicAdd(pc + 0, acc.x);
        atomicAdd(pc + 1, acc.y);
        atomicAdd(pc + 2, acc.z);
        atomicAdd(pc + 3, acc.w);
    }
    __syncthreads();

    // softmax: warp w (0..7) handles patch pw = xh*8 + w; write transposed
    const int wid = tid >> 5, lane = tid & 31;
    if (wid < 8) {
        const int pw = xh * 8 + wid;
        const float m   = (__ldg(du + (b * FN + ph) * FN + pw) > DROP_P) ? 1.f : 0.f;
        const float abv = __ldg(ab);
        const int p0 = lane, p1 = lane + 32;
        float v0 = -1e30f, v1 = -1e30f;
        if (p0 < NP) {
            int d = p0 / KS, e = p0 - d * KS;
            v0 = (pd_s[d * 56 + wid * KS + e] + abv) * m * __ldg(wmat + p0) + __ldg(bmat + p0);
        }
        if (p1 < NP) {
            int d = p1 / KS, e = p1 - d * KS;
            v1 = (pd_s[d * 56 + wid * KS + e] + abv) * m * __ldg(wmat + p1) + __ldg(bmat + p1);
        }
        float mx = fmaxf(v0, v1);
        #pragma unroll
        for (int o = 16; o; o >>= 1)
            mx = fmaxf(mx, __shfl_xor_sync(0xffffffffu, mx, o));
        float e0 = (p0 < NP) ? __expf(v0 - mx) : 0.f;
        float e1 = (p1 < NP) ? __expf(v1 - mx) : 0.f;
        float ss = e0 + e1;
        #pragma unroll
        for (int o = 16; o; o >>= 1)
            ss += __shfl_xor_sync(0xffffffffu, ss, o);
        const float inv = 1.f / ss;
        float* dstT = g_attnT + (size_t)slab * SLABPIX;
        if (p0 < NP) {
            int d = p0 / KS, e = p0 - d * KS;
            dstT[d * HW + pw * KS + e] = e0 * inv;
        }
        if (p1 < NP) {
            int d = p1 / KS, e = p1 - d * KS;
            dstT[d * HW + pw * KS + e] = e1 * inv;
        }
    }
}

// ================= K3: register epilogue, transposed coefs ===============
__global__ void __launch_bounds__(T3, 2)
k3_epilogue(const float* __restrict__ hr, float* __restrict__ out,
            int slab_base)
{
    __shared__ float out_s[CPGO * FN];

    const int bid   = blockIdx.x;
    const int slab  = slab_base + bid / NCG2;
    const int cg    = bid - (bid / NCG2) * NCG2;
    const int ph    = slab & (FN - 1);
    const int b     = slab >> 4;
    const int cbase = cg * CPGO;

    const int tid = threadIdx.x;
    const int x4  = tid % 28;
    const int cc  = tid / 28;

    for (int i = tid; i < CPGO * FN; i += T3) out_s[i] = 0.f;

    const float4* cp = (const float4*)(g_attnT + (size_t)slab * SLABPIX) + x4;
    float4 coef[KS];
    #pragma unroll
    for (int d = 0; d < KS; d++)
        coef[d] = __ldg(cp + d * 28);

    int pwk[4];
    #pragma unroll
    for (int k = 0; k < 4; k++) pwk[k] = (4 * x4 + k) / KS;

    const float* base = hr + (size_t)(b * DIM + cbase + cc) * PLANE
                           + (size_t)(ph * KS) * HW;
    __syncthreads();

    #pragma unroll
    for (int g = 0; g < 2; g++) {
        const float4* gp = (const float4*)(base + (size_t)(g * 16) * PLANE) + x4;
        float4 v[KS];
        #pragma unroll
        for (int d = 0; d < KS; d++)
            v[d] = __ldg(gp + d * 28);

        float acc[4] = {0.f, 0.f, 0.f, 0.f};
        #pragma unroll
        for (int d = 0; d < KS; d++) {
            acc[0] = fmaf(v[d].x, coef[d].x, acc[0]);
            acc[1] = fmaf(v[d].y, coef[d].y, acc[1]);
            acc[2] = fmaf(v[d].z, coef[d].z, acc[2]);
            acc[3] = fmaf(v[d].w, coef[d].w, acc[3]);
        }
        float* orow = out_s + (g * 16 + cc) * FN;
        int   cur = pwk[0];
        float a   = acc[0];
        #pragma unroll
        for (int k = 1; k < 4; k++) {
            if (pwk[k] == cur) a += acc[k];
            else { atomicAdd(&orow[cur], a); cur = pwk[k]; a = acc[k]; }
        }
        atomicAdd(&orow[cur], a);
    }
    __syncthreads();

    for (int i = tid; i < CPGO * FN; i += T3) {
        const int lc = i >> 4, pw = i & 15;
        out[((size_t)(b * DIM + cbase + lc) * FN + ph) * FN + pw] = out_s[i];
    }
}

extern "C" void kernel_launch(void* const* d_in, const int* in_sizes, int n_in,
                              void* d_out, int out_size)
{
    const float* hr   = (const float*)d_in[0];   // (8,384,112,112)
    // d_in[1] = guidance (unused)
    const float* du   = (const float*)d_in[2];   // (8,16,16,1)
    const float* aw   = (const float*)d_in[3];   // (384,)
    const float* ab   = (const float*)d_in[4];   // (1,)
    const float* wmat = (const float*)d_in[5];   // (7,7)
    const float* bmat = (const float*)d_in[6];   // (7,7)
    float* out = (float*)d_out;                  // (8,384,16,16)

    static cudaStream_t sA = nullptr, sB = nullptr;
    static cudaEvent_t  evStart = nullptr, evEnd = nullptr;
    static cudaEvent_t  evK1[NCHUNK];
    if (!sA) {
        cudaStreamCreateWithFlags(&sA, cudaStreamNonBlocking);
        cudaStreamCreateWithFlags(&sB, cudaStreamNonBlocking);
        cudaEventCreateWithFlags(&evStart, cudaEventDisableTiming);
        cudaEventCreateWithFlags(&evEnd, cudaEventDisableTiming);
        for (int i = 0; i < NCHUNK; i++)
            cudaEventCreateWithFlags(&evK1[i], cudaEventDisableTiming);
    }

    // fork both worker streams off the (captured) launch stream
    cudaEventRecord(evStart, 0);
    cudaStreamWaitEvent(sA, evStart, 0);
    cudaStreamWaitEvent(sB, evStart, 0);

    for (int i = 0; i < NCHUNK; i++) {
        const int sb = i * SLABS_C;
        k1_dot_softmax<<<SLABS_C * 2, 392, 0, sA>>>(hr, du, aw, ab, wmat, bmat, sb);
        cudaEventRecord(evK1[i], sA);
        cudaStreamWaitEvent(sB, evK1[i], 0);
        k3_epilogue<<<SLABS_C * NCG2, T3, 0, sB>>>(hr, out, sb);
    }

    // join: sB's last op is ordered after every K1 chunk, so it covers sA too
    cudaEventRecord(evEnd, sB);
    cudaStreamWaitEvent(0, evEnd, 0);
}

// round 16
// speedup vs baseline: 1.5599x; 1.5599x over previous
#include <cuda_runtime.h>
#include <cstdint>

// AttentionDownsampler v14: exactly v9's two proven kernels, with K3
// traversing slabs in DESCENDING order. hr = 154MB vs L2 = 126MB, so:
//   - K1 (ascending) leaves the high slabs resident in L2; K3 descending
//     starts right there -> its early reads are L2 hits.
//   - K3 descending ends at low slabs; the next graph replay's K1 starts
//     at slab 0 -> its early reads are L2 hits too.
// Zero structural change, pure traversal-order alignment.

#define DIM     384
#define KS      7
#define NP      49
#define HW      112
#define PLANE   (HW * HW)
#define PLANE4  (PLANE / 4)
#define FN      16
#define NSLAB   128
#define SLABPIX 784
#define DROP_P  0.2f

#define CPGO    32
#define NCG2    12
#define T3      448               // (x4:28, cc:16)

__device__ float g_attnT[(size_t)NSLAB * SLABPIX];  // [slab][dy*112 + x]

// ================= K1: pixel dot + softmax (half-slab CTAs) ==============
__global__ void __launch_bounds__(392, 2)
k1_dot_softmax(const float* __restrict__ hr,
               const float* __restrict__ du,
               const float* __restrict__ aw,
               const float* __restrict__ ab,
               const float* __restrict__ wmat,
               const float* __restrict__ bmat)
{
    __shared__ float awsh[DIM];
    __shared__ float pd_s[392];

    const int bid  = blockIdx.x;
    const int xh   = bid & 1;            // x half: columns [xh*56, xh*56+56)
    const int slab = bid >> 1;
    const int ph   = slab & (FN - 1);
    const int b    = slab >> 4;

    const int tid = threadIdx.x;         // tid = qr*98 + dy*14 + x4l
    const int qr  = tid / 98;            // channel quarter 0..3
    const int pos = tid - qr * 98;
    const int dy  = pos / 14;
    const int x4l = pos - dy * 14;

    if (tid < DIM) awsh[tid] = __ldg(aw + tid);
    pd_s[tid] = 0.f;
    __syncthreads();

    const float4* gp = (const float4*)(hr
        + (size_t)(b * DIM + qr * 96) * PLANE
        + (size_t)(ph * KS + dy) * HW) + (xh * 14 + x4l);
    const float* ap = awsh + qr * 96;
    float4 acc = make_float4(0.f, 0.f, 0.f, 0.f);
    #pragma unroll 8
    for (int t = 0; t < 96; t++) {
        float4 v = __ldg(gp + (size_t)t * PLANE4);
        const float a = ap[t];
        acc.x = fmaf(v.x, a, acc.x);
        acc.y = fmaf(v.y, a, acc.y);
        acc.z = fmaf(v.z, a, acc.z);
        acc.w = fmaf(v.w, a, acc.w);
    }
    {
        float* pc = pd_s + dy * 56 + x4l * 4;    // 4 qr contributors per cell
        atomicAdd(pc + 0, acc.x);
        atomicAdd(pc + 1, acc.y);
        atomicAdd(pc + 2, acc.z);
        atomicAdd(pc + 3, acc.w);
    }
    __syncthreads();

    // softmax: warp w (0..7) handles patch pw = xh*8 + w; write TRANSPOSED
    const int wid = tid >> 5, lane = tid & 31;
    if (wid < 8) {
        const int pw = xh * 8 + wid;
        const float m   = (__ldg(du + (b * FN + ph) * FN + pw) > DROP_P) ? 1.f : 0.f;
        const float abv = __ldg(ab);
        const int p0 = lane, p1 = lane + 32;
        float v0 = -1e30f, v1 = -1e30f;
        if (p0 < NP) {
            int d = p0 / KS, e = p0 - d * KS;
            v0 = (pd_s[d * 56 + wid * KS + e] + abv) * m * __ldg(wmat + p0) + __ldg(bmat + p0);
        }
        if (p1 < NP) {
            int d = p1 / KS, e = p1 - d * KS;
            v1 = (pd_s[d * 56 + wid * KS + e] + abv) * m * __ldg(wmat + p1) + __ldg(bmat + p1);
        }
        float mx = fmaxf(v0, v1);
        #pragma unroll
        for (int o = 16; o; o >>= 1)
            mx = fmaxf(mx, __shfl_xor_sync(0xffffffffu, mx, o));
        float e0 = (p0 < NP) ? __expf(v0 - mx) : 0.f;
        float e1 = (p1 < NP) ? __expf(v1 - mx) : 0.f;
        float ss = e0 + e1;
        #pragma unroll
        for (int o = 16; o; o >>= 1)
            ss += __shfl_xor_sync(0xffffffffu, ss, o);
        const float inv = 1.f / ss;
        float* dstT = g_attnT + (size_t)slab * SLABPIX;
        if (p0 < NP) {
            int d = p0 / KS, e = p0 - d * KS;
            dstT[d * HW + pw * KS + e] = e0 * inv;
        }
        if (p1 < NP) {
            int d = p1 / KS, e = p1 - d * KS;
            dstT[d * HW + pw * KS + e] = e1 * inv;
        }
    }
}

// ======== K3: register epilogue, transposed coefs, slab DESCENDING =======
__global__ void __launch_bounds__(T3, 2)
k3_epilogue(const float* __restrict__ hr, float* __restrict__ out)
{
    __shared__ float out_s[CPGO * FN];   // [32ch][16pw]

    const int bid   = blockIdx.x;
    const int slab  = (NSLAB - 1) - bid / NCG2;          // descending slabs
    const int cg    = (NCG2 - 1) - (bid - (bid / NCG2) * NCG2);
    const int ph    = slab & (FN - 1);
    const int b     = slab >> 4;
    const int cbase = cg * CPGO;

    const int tid = threadIdx.x;
    const int x4  = tid % 28;            // float4 column
    const int cc  = tid / 28;            // channel phase 0..15

    for (int i = tid; i < CPGO * FN; i += T3) out_s[i] = 0.f;

    // 7 aligned float4 coefficient loads (L2-hot, shared by 12 CTAs)
    const float4* cp = (const float4*)(g_attnT + (size_t)slab * SLABPIX) + x4;
    float4 coef[KS];
    #pragma unroll
    for (int d = 0; d < KS; d++)
        coef[d] = __ldg(cp + d * 28);

    int pwk[4];
    #pragma unroll
    for (int k = 0; k < 4; k++) pwk[k] = (4 * x4 + k) / KS;

    const float* base = hr + (size_t)(b * DIM + cbase + cc) * PLANE
                           + (size_t)(ph * KS) * HW;
    __syncthreads();                      // out_s zeroed

    #pragma unroll
    for (int g = 0; g < 2; g++) {
        const float4* gp = (const float4*)(base + (size_t)(g * 16) * PLANE) + x4;
        float4 v[KS];
        #pragma unroll
        for (int d = 0; d < KS; d++)
            v[d] = __ldg(gp + d * 28);

        float acc[4] = {0.f, 0.f, 0.f, 0.f};
        #pragma unroll
        for (int d = 0; d < KS; d++) {
            acc[0] = fmaf(v[d].x, coef[d].x, acc[0]);
            acc[1] = fmaf(v[d].y, coef[d].y, acc[1]);
            acc[2] = fmaf(v[d].z, coef[d].z, acc[2]);
            acc[3] = fmaf(v[d].w, coef[d].w, acc[3]);
        }
        float* orow = out_s + (g * 16 + cc) * FN;
        int   cur = pwk[0];
        float a   = acc[0];
        #pragma unroll
        for (int k = 1; k < 4; k++) {
            if (pwk[k] == cur) a += acc[k];
            else { atomicAdd(&orow[cur], a); cur = pwk[k]; a = acc[k]; }
        }
        atomicAdd(&orow[cur], a);
    }
    __syncthreads();

    for (int i = tid; i < CPGO * FN; i += T3) {
        const int lc = i >> 4, pw = i & 15;
        out[((size_t)(b * DIM + cbase + lc) * FN + ph) * FN + pw] = out_s[i];
    }
}

extern "C" void kernel_launch(void* const* d_in, const int* in_sizes, int n_in,
                              void* d_out, int out_size)
{
    const float* hr   = (const float*)d_in[0];   // (8,384,112,112)
    // d_in[1] = guidance (unused)
    const float* du   = (const float*)d_in[2];   // (8,16,16,1)
    const float* aw   = (const float*)d_in[3];   // (384,)
    const float* ab   = (const float*)d_in[4];   // (1,)
    const float* wmat = (const float*)d_in[5];   // (7,7)
    const float* bmat = (const float*)d_in[6];   // (7,7)
    float* out = (float*)d_out;                  // (8,384,16,16)

    k1_dot_softmax<<<NSLAB * 2, 392>>>(hr, du, aw, ab, wmat, bmat);
    k3_epilogue<<<NSLAB * NCG2, T3>>>(hr, out);
}